// round 1
// baseline (speedup 1.0000x reference)
#include <cuda_runtime.h>

// TemporalGCN: per (b,t) tile of B=32,T=512:
//   y1 = A(22x22) @ x(22x192)
//   g1 = relu(y1 @ W0^T + b0)      (W0: [128,192])
//   y2 = A @ g1
//   g2 = relu(y2 @ W1^T + b1)      (W1: [128,128])
//   out[b,t,:] = mean_c g2[c,:]
//
// Persistent-CTA fused kernel, weights resident in SMEM, f32x2 packed FMA.

#define BB 32
#define TT 512
#define CC 22
#define FF 192
#define HH 128
#define NTILES (BB * TT)

#define THREADS 256
#define GRID 148

// SMEM layout (float offsets)
#define P0 194                       // W0^T pitch (even, >=192)
#define P1 130                       // W1^T pitch (even, >=128)
#define OFF_W0 0                     // [128][194] = 24832
#define OFF_W1 (OFF_W0 + HH * P0)    // 24832, [128][130] = 16640
#define OFF_XS (OFF_W1 + HH * P1)    // 41472, 22*192 = 4224
#define OFF_AS (OFF_XS + CC * FF)    // 45696, 484 -> pad 512
#define OFF_Y1 (OFF_AS + 512)        // 46208, 22*192 = 4224
#define OFF_G1 (OFF_Y1 + CC * FF)    // 50432, 22*128 = 2816
#define OFF_Y2 (OFF_G1 + CC * HH)    // 53248, 22*128 = 2816
#define OFF_B0 (OFF_Y2 + CC * HH)    // 56064, 128
#define OFF_B1 (OFF_B0 + HH)         // 56192, 128
#define OFF_PS (OFF_B1 + HH)         // 56320, 256
#define SMEM_FLOATS (OFF_PS + THREADS)   // 56576
#define SMEM_BYTES (SMEM_FLOATS * 4)     // 226304

// Packed f32x2 FMA (FFMA2) — PTX-only form, 2x FFMA throughput on sm_103a.
__device__ __forceinline__ float2 ffma2(float2 a, float2 b, float2 c) {
    float2 d;
    asm("fma.rn.f32x2 %0, %1, %2, %3;"
        : "=l"(*reinterpret_cast<unsigned long long*>(&d))
        : "l"(*reinterpret_cast<const unsigned long long*>(&a)),
          "l"(*reinterpret_cast<const unsigned long long*>(&b)),
          "l"(*reinterpret_cast<const unsigned long long*>(&c)));
    return d;
}

extern "C" __global__ void __launch_bounds__(THREADS, 1)
tgcn_kernel(const float* __restrict__ x, const float* __restrict__ A,
            const float* __restrict__ W0, const float* __restrict__ b0,
            const float* __restrict__ W1, const float* __restrict__ b1,
            float* __restrict__ out)
{
    extern __shared__ float smem[];
    float* Ws0 = smem + OFF_W0;   // [h][k] pitch P0
    float* Ws1 = smem + OFF_W1;   // [h][k] pitch P1
    float* xs  = smem + OFF_XS;   // [j][f]
    float* As  = smem + OFF_AS;   // [c][j]
    float* y1s = smem + OFF_Y1;   // [c][f]
    float* g1s = smem + OFF_G1;   // [c][h]
    float* y2s = smem + OFF_Y2;   // [c][h]
    float* b0s = smem + OFF_B0;
    float* b1s = smem + OFF_B1;
    float* ps  = smem + OFF_PS;

    const int tid = threadIdx.x;

    // ---- Load weights once per CTA (transposed to [h][k]) ----
    for (int idx = tid; idx < HH * FF; idx += THREADS) {
        int h = idx / FF, k = idx - h * FF;
        Ws0[h * P0 + k] = W0[idx];        // coalesced read, conflict-free write
    }
    for (int idx = tid; idx < HH * HH; idx += THREADS) {
        int h = idx >> 7, k = idx & 127;
        Ws1[h * P1 + k] = W1[idx];
    }
    if (tid < HH) { b0s[tid] = b0[tid]; b1s[tid] = b1[tid]; }
    __syncthreads();

    const int h  = tid & 127;
    const int c0 = (tid >> 7) * 11;      // group 0: c 0..10, group 1: c 11..21
    const float* w0row = Ws0 + h * P0;
    const float* w1row = Ws1 + h * P1;

    for (int tile = blockIdx.x; tile < NTILES; tile += gridDim.x) {
        // ---- Load x tile (22x192, contiguous) and A tile (22x22) ----
        {
            const float4* xg = reinterpret_cast<const float4*>(x + (size_t)tile * (CC * FF));
            float4* xs4 = reinterpret_cast<float4*>(xs);
            #pragma unroll 4
            for (int i = tid; i < CC * FF / 4; i += THREADS) xs4[i] = xg[i];
            const float* Ag = A + (size_t)tile * (CC * CC);
            for (int i = tid; i < CC * CC; i += THREADS) As[i] = Ag[i];
        }
        __syncthreads();

        // ---- Phase A: y1[c][f] = sum_j A[c][j] * x[j][f]  (f32x2 over f-pairs) ----
        for (int idx = tid; idx < CC * (FF / 2); idx += THREADS) {
            int c  = idx / (FF / 2);
            int f2 = idx - c * (FF / 2);
            const float* arow = As + c * CC;
            float2 acc = make_float2(0.f, 0.f);
            #pragma unroll
            for (int j = 0; j < CC; j++) {
                float a = arow[j];                                     // broadcast
                float2 xv = *reinterpret_cast<const float2*>(xs + j * FF + 2 * f2);
                acc = ffma2(make_float2(a, a), xv, acc);
            }
            *reinterpret_cast<float2*>(y1s + c * FF + 2 * f2) = acc;
        }
        __syncthreads();

        // ---- Phase B: g1[c][h] = relu(sum_k y1[c][k] * W0[h][k] + b0[h]) ----
        {
            float2 acc[11];
            #pragma unroll
            for (int i = 0; i < 11; i++) acc[i] = make_float2(0.f, 0.f);
            #pragma unroll 4
            for (int k = 0; k < FF; k += 2) {
                float2 w2 = *reinterpret_cast<const float2*>(w0row + k);
                #pragma unroll
                for (int i = 0; i < 11; i++) {
                    float2 yv = *reinterpret_cast<const float2*>(y1s + (c0 + i) * FF + k);
                    acc[i] = ffma2(yv, w2, acc[i]);
                }
            }
            float bb = b0s[h];
            #pragma unroll
            for (int i = 0; i < 11; i++) {
                float v = acc[i].x + acc[i].y + bb;
                g1s[(c0 + i) * HH + h] = fmaxf(v, 0.f);
            }
        }
        __syncthreads();

        // ---- Phase C: y2[c][h] = sum_j A[c][j] * g1[j][h] ----
        {
            float acc[11];
            #pragma unroll
            for (int i = 0; i < 11; i++) acc[i] = 0.f;
            #pragma unroll
            for (int j = 0; j < CC; j++) {
                float gv = g1s[j * HH + h];
                #pragma unroll
                for (int i = 0; i < 11; i++)
                    acc[i] = fmaf(As[(c0 + i) * CC + j], gv, acc[i]);   // A broadcast
            }
            #pragma unroll
            for (int i = 0; i < 11; i++) y2s[(c0 + i) * HH + h] = acc[i];
        }
        __syncthreads();

        // ---- Phase D: psum[h] += relu(sum_k y2[c][k] * W1[h][k] + b1[h]) over c ----
        {
            float2 acc[11];
            #pragma unroll
            for (int i = 0; i < 11; i++) acc[i] = make_float2(0.f, 0.f);
            #pragma unroll 4
            for (int k = 0; k < HH; k += 2) {
                float2 w2 = *reinterpret_cast<const float2*>(w1row + k);
                #pragma unroll
                for (int i = 0; i < 11; i++) {
                    float2 yv = *reinterpret_cast<const float2*>(y2s + (c0 + i) * HH + k);
                    acc[i] = ffma2(yv, w2, acc[i]);
                }
            }
            float bb = b1s[h];
            float s = 0.f;
            #pragma unroll
            for (int i = 0; i < 11; i++)
                s += fmaxf(acc[i].x + acc[i].y + bb, 0.f);
            ps[tid] = s;
        }
        __syncthreads();

        if (tid < HH) {
            float v = (ps[tid] + ps[tid + HH]) * (1.f / (float)CC);
            out[(size_t)tile * HH + tid] = v;
        }
        __syncthreads();
    }
}

extern "C" void kernel_launch(void* const* d_in, const int* in_sizes, int n_in,
                              void* d_out, int out_size)
{
    const float* x  = (const float*)d_in[0];
    const float* A  = (const float*)d_in[1];
    const float* W0 = (const float*)d_in[2];
    const float* b0 = (const float*)d_in[3];
    const float* W1 = (const float*)d_in[4];
    const float* b1 = (const float*)d_in[5];
    float* out = (float*)d_out;

    cudaFuncSetAttribute(tgcn_kernel, cudaFuncAttributeMaxDynamicSharedMemorySize, SMEM_BYTES);
    tgcn_kernel<<<GRID, THREADS, SMEM_BYTES>>>(x, A, W0, b0, W1, b1, out);
}